// round 2
// baseline (speedup 1.0000x reference)
#include <cuda_runtime.h>
#include <math.h>

// Problem dims
#define BB    128
#define NN    256
#define DD    256
#define MSGD  64
#define CDD   32
#define KK    8
#define H1D   128
#define H2D   256
#define BN    (BB*NN)   // 32768

// -------- device scratch (no allocations allowed) --------
__device__ float g_W2p[H1D*MSGD];   // composed W2@Wc@Wd  (128x64)
__device__ float g_b2p[MSGD];       // composed bias
__device__ float g_msgs[BN*MSGD];   // 8 MB
__device__ float g_tmp [BN*DD];     // 32 MB
__device__ float g_scores[(long)BB*NN*NN]; // 32 MB
__device__ float g_agg [BN*MSGD];   // 8 MB

// ============================================================
// 0) Compose W2' = W2@Wc@Wd, b2' = b2@Wc@Wd + bc@Wd + bd
// ============================================================
__global__ void prep_kernel(const float* __restrict__ W2, const float* __restrict__ b2,
                            const float* __restrict__ Wc, const float* __restrict__ bc,
                            const float* __restrict__ Wd, const float* __restrict__ bd) {
    __shared__ float bbuf[CDD];
    int t = threadIdx.x; // 128 threads: one per H1 row
    float T[CDD];
    #pragma unroll
    for (int c = 0; c < CDD; c++) T[c] = 0.f;
    for (int m = 0; m < MSGD; m++) {
        float w = W2[t*MSGD + m];
        #pragma unroll
        for (int c = 0; c < CDD; c++) T[c] += w * Wc[m*CDD + c];
    }
    for (int mm = 0; mm < MSGD; mm++) {
        float acc = 0.f;
        #pragma unroll
        for (int c = 0; c < CDD; c++) acc += T[c] * Wd[c*MSGD + mm];
        g_W2p[t*MSGD + mm] = acc;
    }
    if (t < CDD) {
        float acc = bc[t];
        for (int m = 0; m < MSGD; m++) acc += b2[m] * Wc[m*CDD + t];
        bbuf[t] = acc;
    }
    __syncthreads();
    if (t < MSGD) {
        float acc = bd[t];
        #pragma unroll
        for (int c = 0; c < CDD; c++) acc += bbuf[c] * Wd[c*MSGD + t];
        g_b2p[t] = acc;
    }
}

// ============================================================
// 1) msgs = relu(obs@W1 + b1) @ W2' + b2'   (16 rows per block)
// ============================================================
#define MROWS 16
__global__ __launch_bounds__(128) void msg_kernel(const float* __restrict__ obs,
                                                  const float* __restrict__ W1,
                                                  const float* __restrict__ b1) {
    __shared__ float obs_s[MROWS][DD];   // 16 KB
    __shared__ float h_s[MROWS][H1D];    // 8 KB
    const int t = threadIdx.x;
    const long row0 = (long)blockIdx.x * MROWS;

    // load 16 obs rows (contiguous block)
    {
        const float4* src = (const float4*)(obs + row0 * DD);
        float4* dst = (float4*)(&obs_s[0][0]);
        #pragma unroll
        for (int i = 0; i < (MROWS*DD/4)/128; i++)
            dst[t + i*128] = src[t + i*128];
    }
    __syncthreads();

    // h: 128 cols x 16 rows. thread -> 2 cols x 8 rows.
    {
        const int cg = t & 63;       // col pair base: 2cg, 2cg+1
        const int rg = (t >> 6) * 8; // rows rg..rg+7
        float a0[8], a1[8];
        #pragma unroll
        for (int r = 0; r < 8; r++) { a0[r] = 0.f; a1[r] = 0.f; }
        #pragma unroll 4
        for (int d = 0; d < DD; d++) {
            float2 w = *(const float2*)(W1 + d*H1D + 2*cg);
            #pragma unroll
            for (int r = 0; r < 8; r++) {
                float o = obs_s[rg + r][d];
                a0[r] += o * w.x;
                a1[r] += o * w.y;
            }
        }
        float bx = b1[2*cg], by = b1[2*cg+1];
        #pragma unroll
        for (int r = 0; r < 8; r++) {
            float2 hv;
            hv.x = fmaxf(a0[r] + bx, 0.f);
            hv.y = fmaxf(a1[r] + by, 0.f);
            *(float2*)(&h_s[rg + r][2*cg]) = hv;
        }
    }
    __syncthreads();

    // msgs: 64 cols x 16 rows. thread -> 2 cols x 4 rows.
    {
        const int cg = t & 31;        // cols 2cg, 2cg+1
        const int rg = (t >> 5) * 4;  // rows rg..rg+3
        float a0[4], a1[4];
        #pragma unroll
        for (int r = 0; r < 4; r++) { a0[r] = 0.f; a1[r] = 0.f; }
        #pragma unroll 4
        for (int k = 0; k < H1D; k++) {
            float2 w = *(const float2*)(&g_W2p[k*MSGD + 2*cg]);
            #pragma unroll
            for (int r = 0; r < 4; r++) {
                float h = h_s[rg + r][k];
                a0[r] += h * w.x;
                a1[r] += h * w.y;
            }
        }
        float bx = g_b2p[2*cg], by = g_b2p[2*cg+1];
        #pragma unroll
        for (int r = 0; r < 4; r++) {
            float2 mv; mv.x = a0[r] + bx; mv.y = a1[r] + by;
            *(float2*)(&g_msgs[(row0 + rg + r)*MSGD + 2*cg]) = mv;
        }
    }
}

// ============================================================
// 2) tmp = obs @ Wbil   (M=32768, K=256, N=256), 64x64x16 tiles
// ============================================================
#define TBM 64
#define TBN 64
#define TBK 16
__global__ __launch_bounds__(256) void gemm_nn(const float* __restrict__ A,
                                               const float* __restrict__ Bw,
                                               float* __restrict__ C,
                                               int Kd, int Nn) {
    __shared__ float As[TBK][TBM];
    __shared__ float Bs[TBK][TBN];
    const int tid = threadIdx.x;
    const int tx = tid & 15, ty = tid >> 4;
    const long bm = (long)blockIdx.y * TBM;
    const int  bn = blockIdx.x * TBN;
    float acc[4][4] = {};
    for (int k0 = 0; k0 < Kd; k0 += TBK) {
        {
            int r = tid >> 2, kq = (tid & 3) * 4;
            float4 v = *(const float4*)(A + (bm + r)*Kd + k0 + kq);
            As[kq+0][r] = v.x; As[kq+1][r] = v.y; As[kq+2][r] = v.z; As[kq+3][r] = v.w;
            int kk = tid >> 4, c4 = (tid & 15) * 4;
            *(float4*)(&Bs[kk][c4]) = *(const float4*)(Bw + (long)(k0+kk)*Nn + bn + c4);
        }
        __syncthreads();
        #pragma unroll
        for (int kk = 0; kk < TBK; kk++) {
            float4 a = *(const float4*)(&As[kk][ty*4]);
            float4 b = *(const float4*)(&Bs[kk][tx*4]);
            acc[0][0] += a.x*b.x; acc[0][1] += a.x*b.y; acc[0][2] += a.x*b.z; acc[0][3] += a.x*b.w;
            acc[1][0] += a.y*b.x; acc[1][1] += a.y*b.y; acc[1][2] += a.y*b.z; acc[1][3] += a.y*b.w;
            acc[2][0] += a.z*b.x; acc[2][1] += a.z*b.y; acc[2][2] += a.z*b.z; acc[2][3] += a.z*b.w;
            acc[3][0] += a.w*b.x; acc[3][1] += a.w*b.y; acc[3][2] += a.w*b.z; acc[3][3] += a.w*b.w;
        }
        __syncthreads();
    }
    #pragma unroll
    for (int i = 0; i < 4; i++) {
        long row = bm + ty*4 + i;
        float4 o; o.x = acc[i][0]; o.y = acc[i][1]; o.z = acc[i][2]; o.w = acc[i][3];
        *(float4*)(C + row*Nn + bn + tx*4) = o;
    }
}

// ============================================================
// 3) scores[b] = tmp[b] @ obs[b]^T + bbil  (per batch 256x256x256)
// ============================================================
__global__ __launch_bounds__(256) void gemm_nt(const float* __restrict__ A,
                                               const float* __restrict__ Bm,
                                               float* __restrict__ C,
                                               const float* __restrict__ bbil) {
    __shared__ float As[TBK][TBM];
    __shared__ float Bs[TBK][TBN];
    const int tid = threadIdx.x;
    const int tx = tid & 15, ty = tid >> 4;
    const int b = blockIdx.z;
    const float* Ab = A + (long)b * NN * DD;
    const float* Bb = Bm + (long)b * NN * DD;
    float* Cb = C + (long)b * NN * NN;
    const int bi = blockIdx.y * TBM;
    const int bj = blockIdx.x * TBN;
    float acc[4][4] = {};
    for (int k0 = 0; k0 < DD; k0 += TBK) {
        {
            int r = tid >> 2, kq = (tid & 3) * 4;
            float4 va = *(const float4*)(Ab + (long)(bi + r)*DD + k0 + kq);
            As[kq+0][r] = va.x; As[kq+1][r] = va.y; As[kq+2][r] = va.z; As[kq+3][r] = va.w;
            float4 vb = *(const float4*)(Bb + (long)(bj + r)*DD + k0 + kq);
            Bs[kq+0][r] = vb.x; Bs[kq+1][r] = vb.y; Bs[kq+2][r] = vb.z; Bs[kq+3][r] = vb.w;
        }
        __syncthreads();
        #pragma unroll
        for (int kk = 0; kk < TBK; kk++) {
            float4 a = *(const float4*)(&As[kk][ty*4]);
            float4 b4 = *(const float4*)(&Bs[kk][tx*4]);
            acc[0][0] += a.x*b4.x; acc[0][1] += a.x*b4.y; acc[0][2] += a.x*b4.z; acc[0][3] += a.x*b4.w;
            acc[1][0] += a.y*b4.x; acc[1][1] += a.y*b4.y; acc[1][2] += a.y*b4.z; acc[1][3] += a.y*b4.w;
            acc[2][0] += a.z*b4.x; acc[2][1] += a.z*b4.y; acc[2][2] += a.z*b4.z; acc[2][3] += a.z*b4.w;
            acc[3][0] += a.w*b4.x; acc[3][1] += a.w*b4.y; acc[3][2] += a.w*b4.z; acc[3][3] += a.w*b4.w;
        }
        __syncthreads();
    }
    const float bv = *bbil;
    #pragma unroll
    for (int i = 0; i < 4; i++) {
        int row = bi + ty*4 + i;
        float4 o; o.x = acc[i][0]+bv; o.y = acc[i][1]+bv; o.z = acc[i][2]+bv; o.w = acc[i][3]+bv;
        *(float4*)(Cb + (long)row*NN + bj + tx*4) = o;
    }
}

// ============================================================
// 4) top-8 + softmax + weighted gather of msgs -> agg
//    one warp per (b,i) row; tie-break = lowest index (matches lax.top_k)
// ============================================================
__global__ __launch_bounds__(256) void topk_agg_kernel() {
    const int warp = threadIdx.x >> 5, lane = threadIdx.x & 31;
    const long row = (long)blockIdx.x * 8 + warp;  // < BN
    const int b = (int)(row >> 8);
    const float* srow = g_scores + row * NN;

    float v[8]; int idx[8]; unsigned used = 0;
    #pragma unroll
    for (int q = 0; q < 8; q++) { idx[q] = q*32 + lane; v[q] = srow[q*32 + lane]; }

    float topv[KK]; int topi[KK];
    #pragma unroll
    for (int it = 0; it < KK; it++) {
        float bv = -INFINITY; int bi = 1 << 30;
        #pragma unroll
        for (int q = 0; q < 8; q++) {
            bool ok = !((used >> q) & 1);
            if (ok && (v[q] > bv || (v[q] == bv && idx[q] < bi))) { bv = v[q]; bi = idx[q]; }
        }
        #pragma unroll
        for (int off = 16; off; off >>= 1) {
            float ov = __shfl_down_sync(0xffffffffu, bv, off);
            int   oi = __shfl_down_sync(0xffffffffu, bi, off);
            if (ov > bv || (ov == bv && oi < bi)) { bv = ov; bi = oi; }
        }
        bv = __shfl_sync(0xffffffffu, bv, 0);
        bi = __shfl_sync(0xffffffffu, bi, 0);
        topv[it] = bv; topi[it] = bi;
        #pragma unroll
        for (int q = 0; q < 8; q++) if (idx[q] == bi) used |= (1u << q);
    }

    // softmax over the 8 (topv[0] is the max)
    float e[KK]; float s = 0.f;
    #pragma unroll
    for (int it = 0; it < KK; it++) { e[it] = expf(topv[it] - topv[0]); s += e[it]; }
    const float inv = 1.f / s;

    float a0 = 0.f, a1 = 0.f;
    #pragma unroll
    for (int it = 0; it < KK; it++) {
        const float* mrow = g_msgs + ((long)b * NN + topi[it]) * MSGD;
        float g = e[it] * inv;
        a0 += g * mrow[lane];
        a1 += g * mrow[lane + 32];
    }
    g_agg[row*MSGD + lane]      = a0;
    g_agg[row*MSGD + lane + 32] = a1;
}

// ============================================================
// 5) receiver: out = relu([obs,agg]@Wr1 + br1)@Wr2 + br2
//    16 rows/block, thread -> 2 cols x 8 rows
// ============================================================
#define RROWS 16
__global__ __launch_bounds__(256) void recv_kernel(const float* __restrict__ obs,
                                                   const float* __restrict__ Wr1,
                                                   const float* __restrict__ br1,
                                                   const float* __restrict__ Wr2,
                                                   const float* __restrict__ br2,
                                                   float* __restrict__ out) {
    __shared__ float comb[RROWS][DD + MSGD]; // 16x320 = 20 KB
    __shared__ float rs[RROWS][H2D];         // 16x256 = 16 KB
    const int t = threadIdx.x;               // 256
    const long row0 = (long)blockIdx.x * RROWS;

    // load obs (256) and agg (64) per row
    #pragma unroll
    for (int i = t; i < RROWS*DD/4; i += 256) {
        int r = i >> 6, c = i & 63;
        ((float4*)&comb[r][0])[c] = ((const float4*)(obs + (row0 + r)*DD))[c];
    }
    #pragma unroll
    for (int i = t; i < RROWS*MSGD/4; i += 256) {
        int r = i >> 4, c = i & 15;
        ((float4*)&comb[r][DD])[c] = ((const float4*)(g_agg + (row0 + r)*MSGD))[c];
    }
    __syncthreads();

    const int cg = t & 127;        // cols 2cg, 2cg+1
    const int rg = (t >> 7) * 8;   // rows rg..rg+7

    // phase 1: r = relu(comb @ Wr1 + br1)
    {
        float a0[8], a1[8];
        #pragma unroll
        for (int r = 0; r < 8; r++) { a0[r] = 0.f; a1[r] = 0.f; }
        #pragma unroll 4
        for (int c = 0; c < DD + MSGD; c++) {
            float2 w = *(const float2*)(Wr1 + c*H2D + 2*cg);
            #pragma unroll
            for (int r = 0; r < 8; r++) {
                float x = comb[rg + r][c];
                a0[r] += x * w.x;
                a1[r] += x * w.y;
            }
        }
        float bx = br1[2*cg], by = br1[2*cg+1];
        #pragma unroll
        for (int r = 0; r < 8; r++) {
            float2 hv;
            hv.x = fmaxf(a0[r] + bx, 0.f);
            hv.y = fmaxf(a1[r] + by, 0.f);
            *(float2*)(&rs[rg + r][2*cg]) = hv;
        }
    }
    __syncthreads();

    // phase 2: out = rs @ Wr2 + br2
    {
        float a0[8], a1[8];
        #pragma unroll
        for (int r = 0; r < 8; r++) { a0[r] = 0.f; a1[r] = 0.f; }
        #pragma unroll 4
        for (int k = 0; k < H2D; k++) {
            float2 w = *(const float2*)(Wr2 + k*DD + 2*cg);
            #pragma unroll
            for (int r = 0; r < 8; r++) {
                float x = rs[rg + r][k];
                a0[r] += x * w.x;
                a1[r] += x * w.y;
            }
        }
        float bx = br2[2*cg], by = br2[2*cg+1];
        #pragma unroll
        for (int r = 0; r < 8; r++) {
            float2 o; o.x = a0[r] + bx; o.y = a1[r] + by;
            *(float2*)(out + (row0 + rg + r)*DD + 2*cg) = o;
        }
    }
}

// ============================================================
extern "C" void kernel_launch(void* const* d_in, const int* in_sizes, int n_in,
                              void* d_out, int out_size) {
    const float* obs  = (const float*)d_in[0];
    const float* W1   = (const float*)d_in[1];
    const float* b1   = (const float*)d_in[2];
    const float* W2   = (const float*)d_in[3];
    const float* b2   = (const float*)d_in[4];
    const float* Wc   = (const float*)d_in[5];
    const float* bc   = (const float*)d_in[6];
    const float* Wd   = (const float*)d_in[7];
    const float* bd   = (const float*)d_in[8];
    const float* Wbil = (const float*)d_in[9];
    const float* bbil = (const float*)d_in[10];
    const float* Wr1  = (const float*)d_in[11];
    const float* br1  = (const float*)d_in[12];
    const float* Wr2  = (const float*)d_in[13];
    const float* br2  = (const float*)d_in[14];
    float* out = (float*)d_out;

    float* tmp;    cudaGetSymbolAddress((void**)&tmp,    g_tmp);
    float* scores; cudaGetSymbolAddress((void**)&scores, g_scores);

    prep_kernel<<<1, 128>>>(W2, b2, Wc, bc, Wd, bd);
    msg_kernel<<<BN / MROWS, 128>>>(obs, W1, b1);
    {
        dim3 grid(DD / TBN, BN / TBM);
        gemm_nn<<<grid, 256>>>(obs, Wbil, tmp, DD, DD);
    }
    {
        dim3 grid(NN / TBN, NN / TBM, BB);
        gemm_nt<<<grid, 256>>>(tmp, obs, scores, bbil);
    }
    topk_agg_kernel<<<BN / 8, 256>>>();
    recv_kernel<<<BN / RROWS, 256>>>(obs, Wr1, br1, Wr2, br2, out);
}